// round 17
// baseline (speedup 1.0000x reference)
#include <cuda_runtime.h>
#include <cstdint>

#define FEATURES     2048
#define F4           (FEATURES / 4)      // 512 float4 per row
#define SCALE        4.0f
#define TPB          512
#define STAGES       4
#define STAGE_FLOATS 4096                // 2 rows per stage
#define STAGE_F4     (STAGE_FLOATS / 4)  // 1024 float4
#define STAGE_BYTES  (STAGE_FLOATS * 4)  // 16 KB
#define ITERS        8                   // stages per CTA
#define GRID         2048                // 2048*8*4096 = 67,108,864 floats
#define SMEM_BYTES   (STAGES * STAGE_BYTES + STAGES * 8 + 64)

// out = sigmoid(SCALE*(x*w[f]+b[f])) over [32768,2048] fp32. HBM-bound.
//
// R16: break the register-file bound on in-flight loads. cp.async.bulk (TMA
// bulk, zero register cost) fills a 4-stage x 16KB smem ring; 3 CTAs/SM give
// ~192 KB/SM of staged read data vs the ~128 KB RF ceiling of the LDG
// versions. Consumers: conflict-free LDS.128 -> FFMA+MUFU.TANH+FFMA ->
// STG.128 .cs. Stage = 2 rows, so thread t's feature float4 is t for both
// halves: one register (w,b) pair, SCALE/2 folded, zero index math.

__device__ __forceinline__ float tanh_approx(float z) {
    float t;
    asm("tanh.approx.f32 %0, %1;" : "=f"(t) : "f"(z));
    return t;
}

__device__ __forceinline__ uint32_t smem_u32(const void* p) {
    return (uint32_t)__cvta_generic_to_shared(p);
}

__device__ __forceinline__ void mbar_init(uint32_t mbar, uint32_t count) {
    asm volatile("mbarrier.init.shared.b64 [%0], %1;" :: "r"(mbar), "r"(count) : "memory");
}

__device__ __forceinline__ void mbar_expect_tx(uint32_t mbar, uint32_t bytes) {
    asm volatile("mbarrier.arrive.expect_tx.shared.b64 _, [%0], %1;"
                 :: "r"(mbar), "r"(bytes) : "memory");
}

__device__ __forceinline__ void mbar_wait_parity(uint32_t mbar, uint32_t parity) {
    asm volatile(
        "{\n\t"
        ".reg .pred P;\n\t"
        "WAIT_%=:\n\t"
        "mbarrier.try_wait.parity.acquire.cta.shared::cta.b64 P, [%0], %1, 0x989680;\n\t"
        "@P bra DONE_%=;\n\t"
        "bra WAIT_%=;\n\t"
        "DONE_%=:\n\t"
        "}"
        :: "r"(mbar), "r"(parity) : "memory");
}

__device__ __forceinline__ void bulk_g2s(uint32_t dst_smem, const void* src, uint32_t bytes,
                                         uint32_t mbar) {
    asm volatile(
        "cp.async.bulk.shared::cta.global.mbarrier::complete_tx::bytes [%0], [%1], %2, [%3];"
        :: "r"(dst_smem), "l"(src), "r"(bytes), "r"(mbar) : "memory");
}

__global__ void __launch_bounds__(TPB, 3) onetoone_sigmoid_bulk(
    const float4* __restrict__ x,
    const float4* __restrict__ w,
    const float4* __restrict__ b,
    float4* __restrict__ out)
{
    extern __shared__ float4 smem[];                 // [STAGES][STAGE_F4] + barriers
    const int tid = threadIdx.x;                     // 0..511 == feature float4 idx
    uint32_t mbar0 = smem_u32(smem) + STAGES * STAGE_BYTES;

    if (tid == 0) {
        #pragma unroll
        for (int s = 0; s < STAGES; s++) mbar_init(mbar0 + 8 * s, 1);
    }
    __syncthreads();
    asm volatile("fence.proxy.async.shared::cta;" ::: "memory");

    // One (w,b) float4 per thread, SCALE/2 = 2.0 folded in once.
    float4 wv = __ldg(&w[tid]);
    float4 bv = __ldg(&b[tid]);
    wv.x *= 2.0f; wv.y *= 2.0f; wv.z *= 2.0f; wv.w *= 2.0f;
    bv.x *= 2.0f; bv.y *= 2.0f; bv.z *= 2.0f; bv.w *= 2.0f;

    const int chunk4 = blockIdx.x * (ITERS * STAGE_F4);   // CTA base, float4 units
    const float4* xg = x + chunk4;
    float4*       og = out + chunk4;

    // Prologue: fill the ring.
    if (tid == 0) {
        #pragma unroll
        for (int s = 0; s < STAGES; s++) {
            mbar_expect_tx(mbar0 + 8 * s, STAGE_BYTES);
            bulk_g2s(smem_u32(smem) + s * STAGE_BYTES, xg + s * STAGE_F4,
                     STAGE_BYTES, mbar0 + 8 * s);
        }
    }

    #pragma unroll 1
    for (int i = 0; i < ITERS; i++) {
        const int slot   = i & (STAGES - 1);
        const uint32_t ph = (i / STAGES) & 1;
        mbar_wait_parity(mbar0 + 8 * slot, ph);

        // Conflict-free: 16B thread stride; two halves 8KB apart (same feature row pos).
        const float4* st = smem + slot * STAGE_F4;
        float4 xa = st[tid];
        float4 xc = st[tid + (STAGE_F4 / 2)];

        float4 ra, rc;
        ra.x = fmaf(tanh_approx(fmaf(xa.x, wv.x, bv.x)), 0.5f, 0.5f);
        ra.y = fmaf(tanh_approx(fmaf(xa.y, wv.y, bv.y)), 0.5f, 0.5f);
        ra.z = fmaf(tanh_approx(fmaf(xa.z, wv.z, bv.z)), 0.5f, 0.5f);
        ra.w = fmaf(tanh_approx(fmaf(xa.w, wv.w, bv.w)), 0.5f, 0.5f);
        rc.x = fmaf(tanh_approx(fmaf(xc.x, wv.x, bv.x)), 0.5f, 0.5f);
        rc.y = fmaf(tanh_approx(fmaf(xc.y, wv.y, bv.y)), 0.5f, 0.5f);
        rc.z = fmaf(tanh_approx(fmaf(xc.z, wv.z, bv.z)), 0.5f, 0.5f);
        rc.w = fmaf(tanh_approx(fmaf(xc.w, wv.w, bv.w)), 0.5f, 0.5f);

        __stcs(&og[i * STAGE_F4 + tid], ra);
        __stcs(&og[i * STAGE_F4 + tid + (STAGE_F4 / 2)], rc);

        // All threads done with this slot -> refill it with stage i+STAGES.
        __syncthreads();
        if (tid == 0 && i + STAGES < ITERS) {
            mbar_expect_tx(mbar0 + 8 * slot, STAGE_BYTES);
            bulk_g2s(smem_u32(smem) + slot * STAGE_BYTES,
                     xg + (i + STAGES) * STAGE_F4, STAGE_BYTES, mbar0 + 8 * slot);
        }
    }
}

// Generic guarded fallback (only used if sizes ever change).
__global__ void __launch_bounds__(256) onetoone_sigmoid_generic(
    const float4* __restrict__ x,
    const float4* __restrict__ w,
    const float4* __restrict__ b,
    float4* __restrict__ out,
    int total4)
{
    int i = blockIdx.x * blockDim.x + threadIdx.x;
    if (i >= total4) return;
    int fi = i & (F4 - 1);
    float4 xv = __ldcs(&x[i]);
    float4 wv = __ldg(&w[fi]);
    float4 bv = __ldg(&b[fi]);
    float4 r;
    r.x = fmaf(tanh_approx(2.0f * fmaf(xv.x, wv.x, bv.x)), 0.5f, 0.5f);
    r.y = fmaf(tanh_approx(2.0f * fmaf(xv.y, wv.y, bv.y)), 0.5f, 0.5f);
    r.z = fmaf(tanh_approx(2.0f * fmaf(xv.z, wv.z, bv.z)), 0.5f, 0.5f);
    r.w = fmaf(tanh_approx(2.0f * fmaf(xv.w, wv.w, bv.w)), 0.5f, 0.5f);
    __stcs(&out[i], r);
}

extern "C" void kernel_launch(void* const* d_in, const int* in_sizes, int n_in,
                              void* d_out, int out_size)
{
    const float4* x = (const float4*)d_in[0];   // input  [N, FEATURES] fp32
    const float4* w = (const float4*)d_in[1];   // weight [FEATURES]    fp32
    const float4* b = (const float4*)d_in[2];   // bias   [FEATURES]    fp32
    float4* out = (float4*)d_out;

    if (out_size == GRID * ITERS * STAGE_FLOATS && in_sizes[1] == FEATURES) {
        static bool attr_set = false;
        if (!attr_set) {
            cudaFuncSetAttribute(onetoone_sigmoid_bulk,
                                 cudaFuncAttributeMaxDynamicSharedMemorySize, SMEM_BYTES);
            attr_set = true;
        }
        onetoone_sigmoid_bulk<<<GRID, TPB, SMEM_BYTES>>>(x, w, b, out);
    } else {
        int total4 = out_size / 4;
        int blocks = (total4 + 255) / 256;
        onetoone_sigmoid_generic<<<blocks, 256>>>(x, w, b, out, total4);
    }
}